// round 12
// baseline (speedup 1.0000x reference)
#include <cuda_runtime.h>

// ============================================================================
// AdaMLP fused persistent kernel (R11 = R8 structure + DETERMINISTIC grouping).
// 1024 slots, 64 experts, 256 -> 1024(relu) -> 256, fp32 exact (FFMA2).
//
// R8/R10 failure root cause: s_list was built with per-CTA atomics, so each
// CTA had a different ordering; the zhalf position-based work split across
// CTA pairs then left some slots covered by NEITHER CTA (stale g_H rows,
// rel_err ~0.2, nondeterministic). Fix: single-warp stable compaction
// (__match_any_sync + lane rank over 32 sequential chunks) -> every CTA
// computes the identical s_list (ascending slot order within each expert).
// ============================================================================

typedef unsigned long long u64;

#define NEXP 64
#define NSLOT 1024
#define DIM 256
#define RDIM 1024
#define SC 8            // slots per chunk (per CTA)
#define SPAD 12         // smem row stride floats (8 + 4; 48B, 16B-aligned)
#define GRID 1024
#define FULLMASK 0xFFFFFFFFu

__device__ float g_H[NSLOT * RDIM];          // 4 MB hidden (post-ReLU)
__device__ float g_P[4 * NSLOT * DIM];       // 4 MB partials (4 r-segments)
__device__ unsigned g_bar_cnt = 0;
__device__ unsigned g_bar_gen = 0;

__device__ __forceinline__ u64 pack2(float x, float y) {
    u64 r; asm("mov.b64 %0, {%1,%2};" : "=l"(r) : "f"(x), "f"(y)); return r;
}
__device__ __forceinline__ void fma2(u64& d, u64 a, u64 b) {
    asm("fma.rn.f32x2 %0, %1, %2, %0;" : "+l"(d) : "l"(a), "l"(b));
}
__device__ __forceinline__ float2 unpack2(u64 v) {
    float lo, hi; asm("mov.b64 {%0,%1}, %2;" : "=f"(lo), "=f"(hi) : "l"(v));
    return make_float2(lo, hi);
}

// Grid-wide barrier (release by all threads, acquire after spin).
__device__ __forceinline__ void grid_barrier() {
    __threadfence();                       // release: every thread's STGs
    __syncthreads();
    if (threadIdx.x == 0) {
        volatile unsigned* genp = &g_bar_gen;
        unsigned g = *genp;
        if (atomicAdd(&g_bar_cnt, 1u) == gridDim.x - 1) {
            g_bar_cnt = 0;
            __threadfence();
            atomicAdd(&g_bar_gen, 1u);
        } else {
            while (*genp == g) { __nanosleep(64); }
        }
        __threadfence();                   // acquire
    }
    __syncthreads();
}

__global__ __launch_bounds__(128, 8) void fused_kernel(
    const float* __restrict__ slots,
    const float* __restrict__ w1,
    const float* __restrict__ b1,
    const float* __restrict__ w2,
    const float* __restrict__ b2,
    const int*   __restrict__ idx,
    float* __restrict__ out)
{
    __shared__ int s_cnt[NEXP];
    __shared__ int s_base[NEXP];
    __shared__ int s_cur[NEXP];
    __shared__ int s_e[NSLOT];
    __shared__ int s_list[NSLOT];
    __shared__ __align__(16) float sbuf[DIM * SPAD];   // 12 KB
    __shared__ int s_flag;

    const int tid = threadIdx.x;
    const int bid = blockIdx.x;

    // ------------- phase 0: DETERMINISTIC per-CTA grouping ------------------
    if (tid < NEXP) s_cnt[tid] = 0;
    if (tid == 0) s_flag = 0;
    __syncthreads();
    for (int t = tid; t < 512; t += 128)
        if (idx[2 * t + 1] != 0) s_flag = 1;    // int64 detect; benign race
    __syncthreads();
    const int flag = s_flag;
    for (int s = tid; s < NSLOT; s += 128) {
        int e = (flag ? idx[s] : idx[2 * s]) & (NEXP - 1);
        s_e[s] = e;
        atomicAdd(&s_cnt[e], 1);                // commutative -> deterministic
    }
    __syncthreads();
    if (tid == 0) {
        int run = 0;
        for (int e = 0; e < NEXP; e++) { s_base[e] = run; run += s_cnt[e]; }
    }
    __syncthreads();
    if (tid < NEXP) s_cur[tid] = s_base[tid];
    __syncthreads();
    // Single-warp stable compaction: 32 sequential chunks of 32 slots.
    // Within a chunk, rank by lane order; chunks processed in slot order.
    // => s_list is ascending-slot within each expert, IDENTICAL in every CTA.
    if (tid < 32) {
        const int lane = tid;
        for (int chunk = 0; chunk < 32; chunk++) {
            int s = chunk * 32 + lane;
            int e = s_e[s];
            unsigned mask = __match_any_sync(FULLMASK, e);
            int leader = __ffs(mask) - 1;
            int old = 0;
            if (lane == leader) old = atomicAdd(&s_cur[e], __popc(mask));
            old = __shfl_sync(FULLMASK, old, leader);
            int rank = __popc(mask & ((1u << lane) - 1u));
            s_list[old + rank] = s;
            __syncwarp();
        }
    }
    __syncthreads();

    // bid decomposition: e = bid>>4; sub = bid&15; zhalf = sub>>3 (slot half)
    const int e_blk = bid >> 4;
    const int sub   = bid & 15;
    const int zhalf = sub >> 3;

    // ---------------- phase 1: GEMM1 (H = relu(slots @ w1 + b1)) ------------
    {
        const int rtile = sub & 7;
        const int n = s_cnt[e_blk], base = s_base[e_blk];
        const int c = rtile * 128 + tid;
        const float* Wp = w1 + (size_t)e_blk * (DIM * RDIM) + c;
        const float bias = b1[(size_t)e_blk * RDIM + c];

        for (int s0 = zhalf * SC; s0 < n; s0 += 2 * SC) {
            const int sc = min(SC, n - s0);
            float va[SC], vb[SC];
#pragma unroll
            for (int j = 0; j < SC; j++) {
                va[j] = 0.0f; vb[j] = 0.0f;
                if (j < sc) {
                    int sj = s_list[base + s0 + j];
                    va[j] = slots[(size_t)sj * DIM + tid];
                    vb[j] = slots[(size_t)sj * DIM + 128 + tid];
                }
            }
            __syncthreads();
#pragma unroll
            for (int j = 0; j < SC; j++) {
                sbuf[tid * SPAD + j] = va[j];
                sbuf[(128 + tid) * SPAD + j] = vb[j];
            }
            __syncthreads();

            u64 acc[4];
#pragma unroll
            for (int p = 0; p < 4; p++) acc[p] = 0ull;

            for (int dd = 0; dd < DIM; dd += 8) {
                float w[8];
#pragma unroll
                for (int i = 0; i < 8; i++) w[i] = Wp[(size_t)(dd + i) * RDIM];
#pragma unroll
                for (int i = 0; i < 8; i++) {
                    u64 ww = pack2(w[i], w[i]);
                    const ulonglong2* sp = (const ulonglong2*)(sbuf + (dd + i) * SPAD);
                    ulonglong2 s01 = sp[0];
                    ulonglong2 s23 = sp[1];
                    fma2(acc[0], s01.x, ww);
                    fma2(acc[1], s01.y, ww);
                    fma2(acc[2], s23.x, ww);
                    fma2(acc[3], s23.y, ww);
                }
            }
#pragma unroll
            for (int q = 0; q < 2; q++) {
                float2 a0 = unpack2(acc[2 * q]);
                float2 a1 = unpack2(acc[2 * q + 1]);
                int j = 4 * q;
                if (j + 0 < sc) g_H[(size_t)s_list[base + s0 + j + 0] * RDIM + c] = fmaxf(a0.x + bias, 0.0f);
                if (j + 1 < sc) g_H[(size_t)s_list[base + s0 + j + 1] * RDIM + c] = fmaxf(a0.y + bias, 0.0f);
                if (j + 2 < sc) g_H[(size_t)s_list[base + s0 + j + 2] * RDIM + c] = fmaxf(a1.x + bias, 0.0f);
                if (j + 3 < sc) g_H[(size_t)s_list[base + s0 + j + 3] * RDIM + c] = fmaxf(a1.y + bias, 0.0f);
            }
            __syncthreads();
        }
    }

    grid_barrier();

    // ---------------- phase 2: GEMM2 partials (P[seg] = H_seg @ w2_seg) -----
    {
        const int seg   = sub & 3;
        const int ctile = (sub >> 2) & 1;
        const int rbase = seg * 256;
        const int c     = ctile * 128 + tid;
        const int n = s_cnt[e_blk], base = s_base[e_blk];
        const float* Wp = w2 + (size_t)e_blk * (RDIM * DIM) + (size_t)rbase * DIM + c;
        float* Pp = g_P + (size_t)seg * (NSLOT * DIM);

        for (int s0 = zhalf * SC; s0 < n; s0 += 2 * SC) {
            const int sc = min(SC, n - s0);
            float va[SC], vb[SC];
#pragma unroll
            for (int j = 0; j < SC; j++) {
                va[j] = 0.0f; vb[j] = 0.0f;
                if (j < sc) {
                    int sj = s_list[base + s0 + j];
                    va[j] = g_H[(size_t)sj * RDIM + rbase + tid];
                    vb[j] = g_H[(size_t)sj * RDIM + rbase + 128 + tid];
                }
            }
            __syncthreads();
#pragma unroll
            for (int j = 0; j < SC; j++) {
                sbuf[tid * SPAD + j] = va[j];
                sbuf[(128 + tid) * SPAD + j] = vb[j];
            }
            __syncthreads();

            u64 acc[4];
#pragma unroll
            for (int p = 0; p < 4; p++) acc[p] = 0ull;

            for (int rr = 0; rr < 256; rr += 8) {
                float w[8];
#pragma unroll
                for (int i = 0; i < 8; i++) w[i] = Wp[(size_t)(rr + i) * DIM];
#pragma unroll
                for (int i = 0; i < 8; i++) {
                    u64 ww = pack2(w[i], w[i]);
                    const ulonglong2* sp = (const ulonglong2*)(sbuf + (rr + i) * SPAD);
                    ulonglong2 s01 = sp[0];
                    ulonglong2 s23 = sp[1];
                    fma2(acc[0], s01.x, ww);
                    fma2(acc[1], s01.y, ww);
                    fma2(acc[2], s23.x, ww);
                    fma2(acc[3], s23.y, ww);
                }
            }
#pragma unroll
            for (int q = 0; q < 2; q++) {
                float2 a0 = unpack2(acc[2 * q]);
                float2 a1 = unpack2(acc[2 * q + 1]);
                int j = 4 * q;
                if (j + 0 < sc) Pp[(size_t)s_list[base + s0 + j + 0] * DIM + c] = a0.x;
                if (j + 1 < sc) Pp[(size_t)s_list[base + s0 + j + 1] * DIM + c] = a0.y;
                if (j + 2 < sc) Pp[(size_t)s_list[base + s0 + j + 2] * DIM + c] = a1.x;
                if (j + 3 < sc) Pp[(size_t)s_list[base + s0 + j + 3] * DIM + c] = a1.y;
            }
            __syncthreads();
        }
    }

    grid_barrier();

    // ---------------- phase 3: reduce partials + b2 -> out (float2) ---------
    {
        int t2 = bid * 128 + tid;                // float2 index; 131072 total
        int slot = t2 >> 7;                      // 128 float2 per slot
        int e = s_e[slot];
        const float2* P2 = (const float2*)g_P;
        const int SEG2 = NSLOT * DIM / 2;
        float2 v0 = P2[t2];
        float2 v1 = P2[SEG2 + t2];
        float2 v2 = P2[2 * SEG2 + t2];
        float2 v3 = P2[3 * SEG2 + t2];
        float2 bb = ((const float2*)b2)[e * 128 + (t2 & 127)];
        float2 r;
        r.x = v0.x + v1.x + v2.x + v3.x + bb.x;
        r.y = v0.y + v1.y + v2.y + v3.y + bb.y;
        ((float2*)out)[t2] = r;
    }
}

// ----------------------------------------------------------------------------
extern "C" void kernel_launch(void* const* d_in, const int* in_sizes, int n_in,
                              void* d_out, int out_size)
{
    const float* slots = (const float*)d_in[0];
    const float* w1    = (const float*)d_in[1];
    const float* b1    = (const float*)d_in[2];
    const float* w2    = (const float*)d_in[3];
    const float* b2    = (const float*)d_in[4];
    const int*   idx   = (const int*)d_in[5];
    float* out = (float*)d_out;

    fused_kernel<<<GRID, 128>>>(slots, w1, b1, w2, b2, idx, out);
}